// round 14
// baseline (speedup 1.0000x reference)
#include <cuda_runtime.h>
#include <cuda_fp16.h>
#include <cstdint>

#define NUM_USERS 100000
#define NUM_ITEMS 50000
#define DIM 64
#define NUM_REL 5
#define TCOLS (NUM_REL * DIM)      // 320
#define WCOLS (TCOLS + 8)          // 328
#define NTILES (WCOLS / 8)         // 41
#define BIN_CAP 320
#define OVF_CAP 65536
#define UPITCH 72                  // smem U-tile pitch in halves (144 B)

__device__ __half g_Ti[(size_t)NUM_ITEMS * TCOLS];          // 32 MB fp16
__device__ __half g_uh[(size_t)NUM_USERS * DIM];            // 12.8 MB fp16
__device__ __half g_ih[(size_t)NUM_ITEMS * DIM];            // 6.4 MB fp16
__device__ uint2  g_WpF[NTILES * 4 * 32];                   // B fragments
__device__ float  g_bi[(size_t)NUM_ITEMS * 8];              // stride 8
__device__ int    g_idx64;
__device__ int    g_cnt[NUM_ITEMS];
__device__ int2   g_pairs[(size_t)NUM_ITEMS * BIN_CAP];     // (user, orig_e)
__device__ int4   g_ovf[OVF_CAP];
__device__ int    g_ovf_cnt;

// ---------------------------------------------------------------------------
// prep: detect index width; zero bin counters; u,i -> fp16; pack W+b fragments.
// ---------------------------------------------------------------------------
__device__ __forceinline__ float wp_elem(const float* W, const float* b,
                                         int col, int k) {
    if (col < TCOLS) {
        int r = col >> 6, c = col & 63;
        return W[(size_t)r * DIM * DIM + (size_t)k * DIM + c];
    }
    int rb = col - TCOLS;
    return (rb < NUM_REL) ? b[(size_t)rb * DIM + k] : 0.0f;
}

__global__ void prep_kernel(const float* __restrict__ uf,
                            const float* __restrict__ itf,
                            const float* __restrict__ W,
                            const float* __restrict__ b,
                            const void* __restrict__ eu) {
    int gid = blockIdx.x * blockDim.x + threadIdx.x;
    if (gid == 0) {
        g_ovf_cnt = 0;
        const int* p = (const int*)eu;
        int is64 = 1;
        #pragma unroll
        for (int j = 1; j < 16; j += 2)
            if (p[j] != 0) is64 = 0;
        g_idx64 = is64;
    }
    if (gid < NUM_ITEMS) g_cnt[gid] = 0;
    if (gid < NUM_USERS * DIM / 4) {
        float4 v = __ldg((const float4*)uf + gid);
        uint2 h;
        __half2 h0 = __floats2half2_rn(v.x, v.y);
        __half2 h1 = __floats2half2_rn(v.z, v.w);
        h.x = *(unsigned*)&h0; h.y = *(unsigned*)&h1;
        ((uint2*)g_uh)[gid] = h;
    }
    if (gid < NUM_ITEMS * DIM / 4) {
        float4 v = __ldg((const float4*)itf + gid);
        uint2 h;
        __half2 h0 = __floats2half2_rn(v.x, v.y);
        __half2 h1 = __floats2half2_rn(v.z, v.w);
        h.x = *(unsigned*)&h0; h.y = *(unsigned*)&h1;
        ((uint2*)g_ih)[gid] = h;
    }
    if (gid < NTILES * 4 * 32) {
        int lane = gid & 31;
        int ks   = (gid >> 5) & 3;
        int nt   = gid >> 7;
        int g = lane >> 2, t = lane & 3;
        int col = nt * 8 + g;
        int k0  = ks * 16 + t * 2;
        __half2 b0 = __floats2half2_rn(wp_elem(W, b, col, k0),
                                       wp_elem(W, b, col, k0 + 1));
        __half2 b1 = __floats2half2_rn(wp_elem(W, b, col, k0 + 8),
                                       wp_elem(W, b, col, k0 + 9));
        uint2 fr;
        fr.x = *(unsigned*)&b0;
        fr.y = *(unsigned*)&b1;
        g_WpF[gid] = fr;
    }
}

// ---------------------------------------------------------------------------
// scatter: one pass into fixed-capacity per-item bins; overflow -> list.
// ---------------------------------------------------------------------------
__global__ void scatter_kernel(const void* __restrict__ edge_u,
                               const void* __restrict__ edge_i, int E) {
    int e = blockIdx.x * blockDim.x + threadIdx.x;
    if (e >= E) return;
    int user, item;
    if (g_idx64) {
        user = (int)__ldg((const long long*)edge_u + e);
        item = (int)__ldg((const long long*)edge_i + e);
    } else {
        user = __ldg((const int*)edge_u + e);
        item = __ldg((const int*)edge_i + e);
    }
    int pos = atomicAdd(&g_cnt[item], 1);
    if (pos < BIN_CAP) {
        g_pairs[(size_t)item * BIN_CAP + pos] = make_int2(user, e);
    } else {
        int op = atomicAdd(&g_ovf_cnt, 1);
        if (op < OVF_CAP) g_ovf[op] = make_int4(user, e, item, 0);
    }
}

// ---------------------------------------------------------------------------
// mma + ldmatrix wrappers
// ---------------------------------------------------------------------------
__device__ __forceinline__ void mma16816(float& c0, float& c1, float& c2, float& c3,
                                         unsigned a0, unsigned a1, unsigned a2, unsigned a3,
                                         unsigned b0, unsigned b1) {
    asm volatile(
        "mma.sync.aligned.m16n8k16.row.col.f32.f16.f16.f32 "
        "{%0,%1,%2,%3}, {%4,%5,%6,%7}, {%8,%9}, {%0,%1,%2,%3};"
        : "+f"(c0), "+f"(c1), "+f"(c2), "+f"(c3)
        : "r"(a0), "r"(a1), "r"(a2), "r"(a3), "r"(b0), "r"(b1));
}

__device__ __forceinline__ void ldmatrix_x4(unsigned& a0, unsigned& a1,
                                            unsigned& a2, unsigned& a3,
                                            uint32_t addr) {
    asm volatile("ldmatrix.sync.aligned.m8n8.x4.shared.b16 {%0,%1,%2,%3}, [%4];"
                 : "=r"(a0), "=r"(a1), "=r"(a2), "=r"(a3) : "r"(addr));
}

__device__ __forceinline__ uint32_t smem_u32(const void* p) {
    return (uint32_t)__cvta_generic_to_shared(p);
}

// ---------------------------------------------------------------------------
// Tensor-core precompute: [Ti | bi] = ih @ Wp^T. A rows are CONSECUTIVE
// (item0..item0+15): stage 2KB coalesced into smem, build fragments via
// ldmatrix (replaces 16 scattered LDG.32 = ~256 wf/warp with ~36 wf/warp).
// ---------------------------------------------------------------------------
__global__ __launch_bounds__(128) void mma_precompute_kernel() {
    __shared__ __half sA[4][16 * UPITCH];           // 4 warps x 2.25 KB
    int warp = (blockIdx.x * blockDim.x + threadIdx.x) >> 5;
    if (warp >= NUM_ITEMS / 16) return;
    int lane = threadIdx.x & 31;
    int g = lane >> 2;
    int t = lane & 3;
    int item0 = warp * 16;
    __half* su = sA[(threadIdx.x >> 5) & 3];

    // Coalesced stage: 16 rows x 64 halves = 128 uint4 contiguous in g_ih.
    const uint4* src = (const uint4*)(g_ih + (size_t)item0 * DIM);
    #pragma unroll
    for (int j = 0; j < 4; j++) {
        int linear = j * 32 + lane;                 // 0..127
        int row = linear >> 3, col = linear & 7;
        *(uint4*)(su + row * UPITCH + col * 8) = __ldg(src + linear);
    }
    __syncwarp();

    uint32_t lmbase = smem_u32(su + (lane & 15) * UPITCH + (lane >> 4) * 8);
    unsigned a[4][4];
    #pragma unroll
    for (int ks = 0; ks < 4; ks++)
        ldmatrix_x4(a[ks][0], a[ks][1], a[ks][2], a[ks][3], lmbase + ks * 32);

    #pragma unroll 4
    for (int nt = 0; nt < NTILES; nt++) {
        float c0 = 0.f, c1 = 0.f, c2 = 0.f, c3 = 0.f;
        const uint2* bf = g_WpF + nt * 4 * 32 + lane;
        #pragma unroll
        for (int ks = 0; ks < 4; ks++) {
            uint2 bb = __ldg(bf + ks * 32);
            mma16816(c0, c1, c2, c3,
                     a[ks][0], a[ks][1], a[ks][2], a[ks][3], bb.x, bb.y);
        }
        if (nt < TCOLS / 8) {
            __half2 h01 = __floats2half2_rn(c0, c1);
            __half2 h23 = __floats2half2_rn(c2, c3);
            int col = nt * 8 + t * 2;
            *(unsigned*)(g_Ti + (size_t)(item0 + g) * TCOLS + col)     = *(unsigned*)&h01;
            *(unsigned*)(g_Ti + (size_t)(item0 + g + 8) * TCOLS + col) = *(unsigned*)&h23;
        } else {
            *(float2*)(g_bi + (size_t)(item0 + g) * 8 + t * 2)     = make_float2(c0, c1);
            *(float2*)(g_bi + (size_t)(item0 + g + 8) * 8 + t * 2) = make_float2(c2, c3);
        }
    }
}

// ---------------------------------------------------------------------------
// Tensor-core edge phase: one warp per item; 16 edges per MMA chunk.
// Double-buffered: chunk s+1's pairs + U rows staged while chunk s computes.
// ---------------------------------------------------------------------------
__global__ __launch_bounds__(256) void edge_mma_kernel(float* __restrict__ out) {
    __shared__ __half sU[8][2][16 * UPITCH];        // 8 warps x 2 bufs x 2.25 KB
    int item = (blockIdx.x * blockDim.x + threadIdx.x) >> 5;
    if (item >= NUM_ITEMS) return;
    int cnt = g_cnt[item];
    if (cnt == 0) return;
    if (cnt > BIN_CAP) cnt = BIN_CAP;
    int nchunks = (cnt + 15) >> 4;

    int wslot = (threadIdx.x >> 5) & 7;
    int lane = threadIdx.x & 31;
    int g = lane >> 2;
    int t = lane & 3;
    const int2* bin = g_pairs + (size_t)item * BIN_CAP;

    // B fragments: B[k][n] = Ti[item][rel n][k] (cols >= 5 zero).
    unsigned bfr[4][2];
    const __half* tb = g_Ti + (size_t)item * TCOLS + g * DIM;
    #pragma unroll
    for (int ks = 0; ks < 4; ks++) {
        if (g < NUM_REL) {
            bfr[ks][0] = *(const unsigned*)(tb + ks * 16 + t * 2);
            bfr[ks][1] = *(const unsigned*)(tb + ks * 16 + t * 2 + 8);
        } else {
            bfr[ks][0] = 0u; bfr[ks][1] = 0u;
        }
    }
    float2 bi2 = *(const float2*)(g_bi + (size_t)item * 8 + t * 2);

    // Prologue: stage chunk 0 into buf 0.
    int idx0 = lane & 15;
    if (idx0 >= cnt) idx0 = cnt - 1;
    int2 pr_cur = __ldg(bin + idx0);
    {
        __half* su = sU[wslot][0];
        #pragma unroll
        for (int it = 0; it < 4; it++) {
            int row = it * 4 + (lane >> 3);
            int u = __shfl_sync(0xffffffffu, pr_cur.x, row);
            uint4 v = __ldg((const uint4*)(g_uh + (size_t)u * DIM) + (lane & 7));
            *(uint4*)(su + row * UPITCH + (lane & 7) * 8) = v;
        }
    }

    for (int ch = 0; ch < nchunks; ch++) {
        int2 pr_next;
        if (ch + 1 < nchunks) {                     // prefetch next chunk
            int idx = (ch + 1) * 16 + (lane & 15);
            if (idx >= cnt) idx = cnt - 1;
            pr_next = __ldg(bin + idx);
            __half* sn = sU[wslot][(ch + 1) & 1];
            #pragma unroll
            for (int it = 0; it < 4; it++) {
                int row = it * 4 + (lane >> 3);
                int u = __shfl_sync(0xffffffffu, pr_next.x, row);
                uint4 v = __ldg((const uint4*)(g_uh + (size_t)u * DIM) + (lane & 7));
                *(uint4*)(sn + row * UPITCH + (lane & 7) * 8) = v;
            }
        }
        __syncwarp();

        __half* su = sU[wslot][ch & 1];
        uint32_t lmbase = smem_u32(su + (lane & 15) * UPITCH + (lane >> 4) * 8);
        float c0 = 0.f, c1 = 0.f, c2 = 0.f, c3 = 0.f;
        #pragma unroll
        for (int ks = 0; ks < 4; ks++) {
            unsigned a0, a1, a2, a3;
            ldmatrix_x4(a0, a1, a2, a3, lmbase + ks * 32);
            mma16816(c0, c1, c2, c3, a0, a1, a2, a3, bfr[ks][0], bfr[ks][1]);
        }

        int s = ch * 16;
        int eg  = __shfl_sync(0xffffffffu, pr_cur.y, g);
        int eg8 = __shfl_sync(0xffffffffu, pr_cur.y, g + 8);
        int col = t * 2;
        bool v0 = (s + g) < cnt;
        bool v8 = (s + g + 8) < cnt;
        if (col < NUM_REL) {
            if (v0) out[(size_t)eg  * NUM_REL + col] = c0 + bi2.x;
            if (v8) out[(size_t)eg8 * NUM_REL + col] = c2 + bi2.x;
            if (col + 1 < NUM_REL) {
                if (v0) out[(size_t)eg  * NUM_REL + col + 1] = c1 + bi2.y;
                if (v8) out[(size_t)eg8 * NUM_REL + col + 1] = c3 + bi2.y;
            }
        }
        pr_cur = pr_next;
    }
}

// ---------------------------------------------------------------------------
// Overflow fallback (expected 0 entries).
// ---------------------------------------------------------------------------
__global__ void overflow_kernel(float* __restrict__ out) {
    int n = g_ovf_cnt;
    if (n > OVF_CAP) n = OVF_CAP;
    for (int i = blockIdx.x * blockDim.x + threadIdx.x; i < n;
         i += gridDim.x * blockDim.x) {
        int4 rec = g_ovf[i];
        const __half* ur = g_uh + (size_t)rec.x * DIM;
        #pragma unroll
        for (int r = 0; r < NUM_REL; r++) {
            const __half* tr = g_Ti + (size_t)rec.z * TCOLS + r * DIM;
            float s = 0.0f;
            for (int k = 0; k < DIM; k++)
                s = fmaf(__half2float(ur[k]), __half2float(tr[k]), s);
            out[(size_t)rec.y * NUM_REL + r] = s + g_bi[(size_t)rec.z * 8 + r];
        }
    }
}

// ---------------------------------------------------------------------------
extern "C" void kernel_launch(void* const* d_in, const int* in_sizes, int n_in,
                              void* d_out, int out_size) {
    const float* uf  = (const float*)d_in[0];
    const float* itf = (const float*)d_in[1];
    const void*  eu  = d_in[2];
    const void*  ei  = d_in[3];
    const float* W   = (const float*)d_in[4];
    const float* b   = (const float*)d_in[5];
    int E = in_sizes[2];

    {
        int n = NUM_USERS * DIM / 4;
        prep_kernel<<<(n + 255) / 256, 256>>>(uf, itf, W, b, eu);
    }
    scatter_kernel<<<(E + 255) / 256, 256>>>(eu, ei, E);
    {
        int warps = NUM_ITEMS / 16;                 // 3125
        int blocks = (warps + 3) / 4;
        mma_precompute_kernel<<<blocks, 128>>>();
    }
    {
        int blocks = (NUM_ITEMS * 32 + 255) / 256;  // one warp per item
        edge_mma_kernel<<<blocks, 256>>>((float*)d_out);
    }
    overflow_kernel<<<32, 256>>>((float*)d_out);
}

// round 15
// speedup vs baseline: 1.0999x; 1.0999x over previous
#include <cuda_runtime.h>
#include <cuda_fp16.h>
#include <cstdint>

#define NUM_USERS 100000
#define NUM_ITEMS 50000
#define DIM 64
#define NUM_REL 5
#define TCOLS (NUM_REL * DIM)      // 320
#define WCOLS (TCOLS + 8)          // 328
#define NTILES (WCOLS / 8)         // 41
#define BIN_CAP 320
#define OVF_CAP 65536
#define UPITCH 72                  // smem U-tile pitch in halves (144 B)

__device__ __half g_Ti[(size_t)NUM_ITEMS * TCOLS];          // 32 MB fp16
__device__ __half g_uh[(size_t)NUM_USERS * DIM];            // 12.8 MB fp16
__device__ __half g_ih[(size_t)NUM_ITEMS * DIM];            // 6.4 MB fp16
__device__ uint2  g_WpF[NTILES * 4 * 32];                   // B fragments
__device__ float  g_bi[(size_t)NUM_ITEMS * 8];              // stride 8
__device__ int    g_idx64;
__device__ int    g_cnt[NUM_ITEMS];
__device__ int2   g_pairs[(size_t)NUM_ITEMS * BIN_CAP];     // (user, orig_e)
__device__ int4   g_ovf[OVF_CAP];
__device__ int    g_ovf_cnt;

// ---------------------------------------------------------------------------
// prep: detect index width; zero bin counters; u,i -> fp16; pack W+b fragments.
// ---------------------------------------------------------------------------
__device__ __forceinline__ float wp_elem(const float* W, const float* b,
                                         int col, int k) {
    if (col < TCOLS) {
        int r = col >> 6, c = col & 63;
        return W[(size_t)r * DIM * DIM + (size_t)k * DIM + c];
    }
    int rb = col - TCOLS;
    return (rb < NUM_REL) ? b[(size_t)rb * DIM + k] : 0.0f;
}

__global__ void prep_kernel(const float* __restrict__ uf,
                            const float* __restrict__ itf,
                            const float* __restrict__ W,
                            const float* __restrict__ b,
                            const void* __restrict__ eu) {
    int gid = blockIdx.x * blockDim.x + threadIdx.x;
    if (gid == 0) {
        g_ovf_cnt = 0;
        const int* p = (const int*)eu;
        int is64 = 1;
        #pragma unroll
        for (int j = 1; j < 16; j += 2)
            if (p[j] != 0) is64 = 0;
        g_idx64 = is64;
    }
    if (gid < NUM_ITEMS) g_cnt[gid] = 0;
    if (gid < NUM_USERS * DIM / 4) {
        float4 v = __ldg((const float4*)uf + gid);
        uint2 h;
        __half2 h0 = __floats2half2_rn(v.x, v.y);
        __half2 h1 = __floats2half2_rn(v.z, v.w);
        h.x = *(unsigned*)&h0; h.y = *(unsigned*)&h1;
        ((uint2*)g_uh)[gid] = h;
    }
    if (gid < NUM_ITEMS * DIM / 4) {
        float4 v = __ldg((const float4*)itf + gid);
        uint2 h;
        __half2 h0 = __floats2half2_rn(v.x, v.y);
        __half2 h1 = __floats2half2_rn(v.z, v.w);
        h.x = *(unsigned*)&h0; h.y = *(unsigned*)&h1;
        ((uint2*)g_ih)[gid] = h;
    }
    if (gid < NTILES * 4 * 32) {
        int lane = gid & 31;
        int ks   = (gid >> 5) & 3;
        int nt   = gid >> 7;
        int g = lane >> 2, t = lane & 3;
        int col = nt * 8 + g;
        int k0  = ks * 16 + t * 2;
        __half2 b0 = __floats2half2_rn(wp_elem(W, b, col, k0),
                                       wp_elem(W, b, col, k0 + 1));
        __half2 b1 = __floats2half2_rn(wp_elem(W, b, col, k0 + 8),
                                       wp_elem(W, b, col, k0 + 9));
        uint2 fr;
        fr.x = *(unsigned*)&b0;
        fr.y = *(unsigned*)&b1;
        g_WpF[gid] = fr;
    }
}

// ---------------------------------------------------------------------------
// scatter: one pass into fixed-capacity per-item bins; overflow -> list.
// ---------------------------------------------------------------------------
__global__ void scatter_kernel(const void* __restrict__ edge_u,
                               const void* __restrict__ edge_i, int E) {
    int e = blockIdx.x * blockDim.x + threadIdx.x;
    if (e >= E) return;
    int user, item;
    if (g_idx64) {
        user = (int)__ldg((const long long*)edge_u + e);
        item = (int)__ldg((const long long*)edge_i + e);
    } else {
        user = __ldg((const int*)edge_u + e);
        item = __ldg((const int*)edge_i + e);
    }
    int pos = atomicAdd(&g_cnt[item], 1);
    if (pos < BIN_CAP) {
        g_pairs[(size_t)item * BIN_CAP + pos] = make_int2(user, e);
    } else {
        int op = atomicAdd(&g_ovf_cnt, 1);
        if (op < OVF_CAP) g_ovf[op] = make_int4(user, e, item, 0);
    }
}

// ---------------------------------------------------------------------------
// mma + ldmatrix wrappers
// ---------------------------------------------------------------------------
__device__ __forceinline__ void mma16816(float& c0, float& c1, float& c2, float& c3,
                                         unsigned a0, unsigned a1, unsigned a2, unsigned a3,
                                         unsigned b0, unsigned b1) {
    asm volatile(
        "mma.sync.aligned.m16n8k16.row.col.f32.f16.f16.f32 "
        "{%0,%1,%2,%3}, {%4,%5,%6,%7}, {%8,%9}, {%0,%1,%2,%3};"
        : "+f"(c0), "+f"(c1), "+f"(c2), "+f"(c3)
        : "r"(a0), "r"(a1), "r"(a2), "r"(a3), "r"(b0), "r"(b1));
}

__device__ __forceinline__ void ldmatrix_x4(unsigned& a0, unsigned& a1,
                                            unsigned& a2, unsigned& a3,
                                            uint32_t addr) {
    asm volatile("ldmatrix.sync.aligned.m8n8.x4.shared.b16 {%0,%1,%2,%3}, [%4];"
                 : "=r"(a0), "=r"(a1), "=r"(a2), "=r"(a3) : "r"(addr));
}

__device__ __forceinline__ uint32_t smem_u32(const void* p) {
    return (uint32_t)__cvta_generic_to_shared(p);
}

// ---------------------------------------------------------------------------
// Tensor-core precompute (R14 ldmatrix version): [Ti | bi] = ih @ Wp^T.
// ---------------------------------------------------------------------------
__global__ __launch_bounds__(128) void mma_precompute_kernel() {
    __shared__ __half sA[4][16 * UPITCH];           // 4 warps x 2.25 KB
    int warp = (blockIdx.x * blockDim.x + threadIdx.x) >> 5;
    if (warp >= NUM_ITEMS / 16) return;
    int lane = threadIdx.x & 31;
    int g = lane >> 2;
    int t = lane & 3;
    int item0 = warp * 16;
    __half* su = sA[(threadIdx.x >> 5) & 3];

    const uint4* src = (const uint4*)(g_ih + (size_t)item0 * DIM);
    #pragma unroll
    for (int j = 0; j < 4; j++) {
        int linear = j * 32 + lane;                 // 0..127
        int row = linear >> 3, col = linear & 7;
        *(uint4*)(su + row * UPITCH + col * 8) = __ldg(src + linear);
    }
    __syncwarp();

    uint32_t lmbase = smem_u32(su + (lane & 15) * UPITCH + (lane >> 4) * 8);
    unsigned a[4][4];
    #pragma unroll
    for (int ks = 0; ks < 4; ks++)
        ldmatrix_x4(a[ks][0], a[ks][1], a[ks][2], a[ks][3], lmbase + ks * 32);

    #pragma unroll 4
    for (int nt = 0; nt < NTILES; nt++) {
        float c0 = 0.f, c1 = 0.f, c2 = 0.f, c3 = 0.f;
        const uint2* bf = g_WpF + nt * 4 * 32 + lane;
        #pragma unroll
        for (int ks = 0; ks < 4; ks++) {
            uint2 bb = __ldg(bf + ks * 32);
            mma16816(c0, c1, c2, c3,
                     a[ks][0], a[ks][1], a[ks][2], a[ks][3], bb.x, bb.y);
        }
        if (nt < TCOLS / 8) {
            __half2 h01 = __floats2half2_rn(c0, c1);
            __half2 h23 = __floats2half2_rn(c2, c3);
            int col = nt * 8 + t * 2;
            *(unsigned*)(g_Ti + (size_t)(item0 + g) * TCOLS + col)     = *(unsigned*)&h01;
            *(unsigned*)(g_Ti + (size_t)(item0 + g + 8) * TCOLS + col) = *(unsigned*)&h23;
        } else {
            *(float2*)(g_bi + (size_t)(item0 + g) * 8 + t * 2)     = make_float2(c0, c1);
            *(float2*)(g_bi + (size_t)(item0 + g + 8) * 8 + t * 2) = make_float2(c2, c3);
        }
    }
}

// ---------------------------------------------------------------------------
// Tensor-core edge phase (R13 single-buffer, measured 64.9us).
// ---------------------------------------------------------------------------
__global__ __launch_bounds__(256) void edge_mma_kernel(float* __restrict__ out) {
    __shared__ __half sU[8][16 * UPITCH];           // 8 warps x 2.25 KB
    int item = (blockIdx.x * blockDim.x + threadIdx.x) >> 5;
    if (item >= NUM_ITEMS) return;
    int cnt = g_cnt[item];
    if (cnt == 0) return;
    if (cnt > BIN_CAP) cnt = BIN_CAP;

    int wslot = (threadIdx.x >> 5) & 7;
    int lane = threadIdx.x & 31;
    int g = lane >> 2;
    int t = lane & 3;
    const int2* bin = g_pairs + (size_t)item * BIN_CAP;
    __half* su = sU[wslot];

    unsigned bfr[4][2];
    const __half* tb = g_Ti + (size_t)item * TCOLS + g * DIM;
    #pragma unroll
    for (int ks = 0; ks < 4; ks++) {
        if (g < NUM_REL) {
            bfr[ks][0] = *(const unsigned*)(tb + ks * 16 + t * 2);
            bfr[ks][1] = *(const unsigned*)(tb + ks * 16 + t * 2 + 8);
        } else {
            bfr[ks][0] = 0u; bfr[ks][1] = 0u;
        }
    }
    float2 bi2 = *(const float2*)(g_bi + (size_t)item * 8 + t * 2);

    uint32_t lmbase = smem_u32(su + (lane & 15) * UPITCH + (lane >> 4) * 8);

    for (int s = 0; s < cnt; s += 16) {
        int idx = s + (lane & 15);
        if (idx >= cnt) idx = cnt - 1;
        int2 pr = __ldg(bin + idx);

        __syncwarp();
        #pragma unroll
        for (int it = 0; it < 4; it++) {
            int row = it * 4 + (lane >> 3);
            int u = __shfl_sync(0xffffffffu, pr.x, row);
            uint4 v = __ldg((const uint4*)(g_uh + (size_t)u * DIM) + (lane & 7));
            *(uint4*)(su + row * UPITCH + (lane & 7) * 8) = v;
        }
        __syncwarp();

        float c0 = 0.f, c1 = 0.f, c2 = 0.f, c3 = 0.f;
        #pragma unroll
        for (int ks = 0; ks < 4; ks++) {
            unsigned a0, a1, a2, a3;
            ldmatrix_x4(a0, a1, a2, a3, lmbase + ks * 32);
            mma16816(c0, c1, c2, c3, a0, a1, a2, a3, bfr[ks][0], bfr[ks][1]);
        }

        int eg  = __shfl_sync(0xffffffffu, pr.y, g);
        int eg8 = __shfl_sync(0xffffffffu, pr.y, g + 8);
        int col = t * 2;
        bool v0 = (s + g) < cnt;
        bool v8 = (s + g + 8) < cnt;
        if (col < NUM_REL) {
            if (v0) out[(size_t)eg  * NUM_REL + col] = c0 + bi2.x;
            if (v8) out[(size_t)eg8 * NUM_REL + col] = c2 + bi2.x;
            if (col + 1 < NUM_REL) {
                if (v0) out[(size_t)eg  * NUM_REL + col + 1] = c1 + bi2.y;
                if (v8) out[(size_t)eg8 * NUM_REL + col + 1] = c3 + bi2.y;
            }
        }
    }
}

// ---------------------------------------------------------------------------
// Overflow fallback (expected 0 entries).
// ---------------------------------------------------------------------------
__global__ void overflow_kernel(float* __restrict__ out) {
    int n = g_ovf_cnt;
    if (n > OVF_CAP) n = OVF_CAP;
    for (int i = blockIdx.x * blockDim.x + threadIdx.x; i < n;
         i += gridDim.x * blockDim.x) {
        int4 rec = g_ovf[i];
        const __half* ur = g_uh + (size_t)rec.x * DIM;
        #pragma unroll
        for (int r = 0; r < NUM_REL; r++) {
            const __half* tr = g_Ti + (size_t)rec.z * TCOLS + r * DIM;
            float s = 0.0f;
            for (int k = 0; k < DIM; k++)
                s = fmaf(__half2float(ur[k]), __half2float(tr[k]), s);
            out[(size_t)rec.y * NUM_REL + r] = s + g_bi[(size_t)rec.z * 8 + r];
        }
    }
}

// ---------------------------------------------------------------------------
// Launch: scatter and mma_precompute are independent (both depend only on
// prep) — run mma_precompute on a side stream, join before edge_mma.
// Streams/events are host objects created once (no device allocation).
// ---------------------------------------------------------------------------
extern "C" void kernel_launch(void* const* d_in, const int* in_sizes, int n_in,
                              void* d_out, int out_size) {
    const float* uf  = (const float*)d_in[0];
    const float* itf = (const float*)d_in[1];
    const void*  eu  = d_in[2];
    const void*  ei  = d_in[3];
    const float* W   = (const float*)d_in[4];
    const float* b   = (const float*)d_in[5];
    int E = in_sizes[2];

    static cudaStream_t s2 = nullptr;
    static cudaEvent_t ev_fork = nullptr, ev_join = nullptr;
    if (!s2) {
        cudaStreamCreateWithFlags(&s2, cudaStreamNonBlocking);
        cudaEventCreateWithFlags(&ev_fork, cudaEventDisableTiming);
        cudaEventCreateWithFlags(&ev_join, cudaEventDisableTiming);
    }
    cudaStream_t s0 = 0;   // harness capture stream (legacy default)

    {
        int n = NUM_USERS * DIM / 4;
        prep_kernel<<<(n + 255) / 256, 256, 0, s0>>>(uf, itf, W, b, eu);
    }
    cudaEventRecord(ev_fork, s0);
    cudaStreamWaitEvent(s2, ev_fork, 0);

    // side stream: precompute Ti/bi
    {
        int warps = NUM_ITEMS / 16;                 // 3125
        int blocks = (warps + 3) / 4;
        mma_precompute_kernel<<<blocks, 128, 0, s2>>>();
    }
    cudaEventRecord(ev_join, s2);

    // main stream: scatter runs concurrently
    scatter_kernel<<<(E + 255) / 256, 256, 0, s0>>>(eu, ei, E);

    cudaStreamWaitEvent(s0, ev_join, 0);
    {
        int blocks = (NUM_ITEMS * 32 + 255) / 256;  // one warp per item
        edge_mma_kernel<<<blocks, 256, 0, s0>>>((float*)d_out);
    }
    overflow_kernel<<<32, 256, 0, s0>>>((float*)d_out);
}